// round 1
// baseline (speedup 1.0000x reference)
#include <cuda_runtime.h>

#define NN 100000
#define EE 1600000
#define LL 3

typedef unsigned long long ull;

// ---------------- device scratch (static, zero-initialized at load) ----------
__device__ float g_agg[NN * 64];      // edge aggregation; invariant: zero at launch entry
__device__ float g_h[NN * 64];        // current hidden state
__device__ float g_z1[NN * 64];       // pre-BN1 activations
__device__ float g_z2[NN * 64];       // pre-BN2 activations
__device__ float g_stats[LL * 256];   // per layer: [sum1(64) sq1(64) sum2(64) sq2(64)]

// ---------------- packed f32x2 helpers ---------------------------------------
__device__ __forceinline__ ull pack2(float a, float b) {
    ull r;
    asm("mov.b64 %0, {%1, %2};" : "=l"(r) : "f"(a), "f"(b));
    return r;
}
__device__ __forceinline__ float2 unpack2(ull v) {
    float2 r;
    asm("mov.b64 {%0, %1}, %2;" : "=f"(r.x), "=f"(r.y) : "l"(v));
    return r;
}
__device__ __forceinline__ void ffma2(ull& d, ull a, ull b) {
    asm("fma.rn.f32x2 %0, %1, %2, %0;" : "+l"(d) : "l"(a), "l"(b));
}

// ---------------- K_init: logits = x @ fcW[0] + sum_l fcb[l]; zero stats -----
__global__ void __launch_bounds__(256) kinit(const float* __restrict__ x,
                                             const float* __restrict__ fcW,
                                             const float* __restrict__ fcb,
                                             float* __restrict__ out) {
    __shared__ float fw[640];
    __shared__ float bsum[10];
    int tid = threadIdx.x;
    for (int i = tid; i < 640; i += 256) fw[i] = fcW[i];
    if (tid < 10) {
        float b = 0.f;
        for (int l = 0; l < LL + 1; l++) b += fcb[l * 10 + tid];
        bsum[tid] = b;
    }
    if (blockIdx.x == 0)
        for (int i = tid; i < LL * 256; i += 256) g_stats[i] = 0.f;
    __syncthreads();
    int n = blockIdx.x * 256 + tid;
    if (n >= NN) return;
    float acc[10];
#pragma unroll
    for (int c = 0; c < 10; c++) acc[c] = bsum[c];
    const float4* x4 = ((const float4*)x) + n * 16;
#pragma unroll
    for (int kk = 0; kk < 16; kk++) {
        float4 v = x4[kk];
        const float* r0 = fw + (kk * 4) * 10;
#pragma unroll
        for (int c = 0; c < 10; c++)
            acc[c] += v.x * r0[c] + v.y * r0[10 + c] + v.z * r0[20 + c] + v.w * r0[30 + c];
    }
#pragma unroll
    for (int c = 0; c < 10; c++) out[n * 10 + c] = acc[c];
}

// ---------------- scatter: agg[dst] += h[src], vectorized fp32 reductions ----
__global__ void __launch_bounds__(256) kscatter(const int* __restrict__ ei,
                                                const float* __restrict__ x,
                                                int use_x) {
    int t = blockIdx.x * 256 + threadIdx.x;
    int e = t >> 4;
    if (e >= EE) return;
    int c = t & 15;
    const float* h = use_x ? x : g_h;
    int s = ei[e];
    int d = ei[EE + e];
    float4 v = *((const float4*)(h + (size_t)s * 64) + c);
    float* p = g_agg + (size_t)d * 64 + c * 4;
    asm volatile("red.global.add.v4.f32 [%0], {%1, %2, %3, %4};"
                 :: "l"(p), "f"(v.x), "f"(v.y), "f"(v.z), "f"(v.w)
                 : "memory");
}

// ---------------- GEMM1: z1 = (h + agg) @ W1 + b1; re-zero agg ---------------
__global__ void __launch_bounds__(256) kgemm1(const float* __restrict__ x, int use_x,
                                              const float* __restrict__ W,
                                              const float* __restrict__ b) {
    __shared__ float4 Ws4[1024];
    __shared__ float bs[64];
    int tid = threadIdx.x;
    const float4* Wg = (const float4*)W;
    for (int i = tid; i < 1024; i += 256) Ws4[i] = Wg[i];
    if (tid < 64) bs[tid] = b[tid];
    __syncthreads();
    int n = blockIdx.x * 256 + tid;
    if (n >= NN) return;
    const float* hin = use_x ? x : g_h;
    ull acc[32];
#pragma unroll
    for (int j = 0; j < 32; j++) acc[j] = pack2(bs[2 * j], bs[2 * j + 1]);
    const float4* h4 = ((const float4*)hin) + n * 16;
    const float4* a4 = ((const float4*)g_agg) + n * 16;
    const ulonglong2* Wv = (const ulonglong2*)Ws4;
#pragma unroll
    for (int kk = 0; kk < 16; kk++) {
        float4 hv = h4[kk];
        float4 av = a4[kk];
        float y[4] = {hv.x + av.x, hv.y + av.y, hv.z + av.z, hv.w + av.w};
#pragma unroll
        for (int t2 = 0; t2 < 4; t2++) {
            ull a2 = pack2(y[t2], y[t2]);
            const ulonglong2* row = Wv + (kk * 4 + t2) * 16;
#pragma unroll
            for (int jj = 0; jj < 16; jj++) {
                ulonglong2 w = row[jj];
                ffma2(acc[2 * jj], a2, w.x);
                ffma2(acc[2 * jj + 1], a2, w.y);
            }
        }
    }
    float4* o4 = ((float4*)g_z1) + n * 16;
#pragma unroll
    for (int m = 0; m < 16; m++) {
        float2 lo = unpack2(acc[2 * m]);
        float2 hi = unpack2(acc[2 * m + 1]);
        o4[m] = make_float4(lo.x, lo.y, hi.x, hi.y);
    }
    float4* ag = ((float4*)g_agg) + n * 16;
    float4 z = make_float4(0.f, 0.f, 0.f, 0.f);
#pragma unroll
    for (int m = 0; m < 16; m++) ag[m] = z;  // restore zero-invariant for next scatter
}

// ---------------- column sums + sums-of-squares over N rows -------------------
__global__ void __launch_bounds__(256) kstats(int which, int layer) {
    const float* z = which ? g_z2 : g_z1;
    float* sums = g_stats + layer * 256 + (which ? 128 : 0);
    __shared__ float4 shS[256];
    __shared__ float4 shQ[256];
    int tid = threadIdx.x;
    int c4 = tid & 15;
    int g = tid >> 4;
    float4 s = make_float4(0.f, 0.f, 0.f, 0.f);
    float4 q = s;
    const float4* z4 = (const float4*)z;
    for (int r = blockIdx.x * 16 + g; r < NN; r += gridDim.x * 16) {
        float4 v = z4[r * 16 + c4];
        s.x += v.x; s.y += v.y; s.z += v.z; s.w += v.w;
        q.x += v.x * v.x; q.y += v.y * v.y; q.z += v.z * v.z; q.w += v.w * v.w;
    }
    shS[tid] = s;
    shQ[tid] = q;
    __syncthreads();
    if (g == 0) {
        for (int gg = 1; gg < 16; gg++) {
            float4 a = shS[c4 + 16 * gg];
            s.x += a.x; s.y += a.y; s.z += a.z; s.w += a.w;
            float4 bq = shQ[c4 + 16 * gg];
            q.x += bq.x; q.y += bq.y; q.z += bq.z; q.w += bq.w;
        }
        atomicAdd(&sums[c4 * 4 + 0], s.x);
        atomicAdd(&sums[c4 * 4 + 1], s.y);
        atomicAdd(&sums[c4 * 4 + 2], s.z);
        atomicAdd(&sums[c4 * 4 + 3], s.w);
        atomicAdd(&sums[64 + c4 * 4 + 0], q.x);
        atomicAdd(&sums[64 + c4 * 4 + 1], q.y);
        atomicAdd(&sums[64 + c4 * 4 + 2], q.z);
        atomicAdd(&sums[64 + c4 * 4 + 3], q.w);
    }
}

// ---------------- GEMM2: z2 = relu(BN1(z1)) @ W2 + b2 ------------------------
__global__ void __launch_bounds__(256) kgemm2(const float* __restrict__ W,
                                              const float* __restrict__ b,
                                              const float* __restrict__ gam,
                                              const float* __restrict__ bet,
                                              int layer) {
    __shared__ float4 Ws4[1024];
    __shared__ float bs[64], sA[64], sB[64];
    int tid = threadIdx.x;
    const float4* Wg = (const float4*)W;
    for (int i = tid; i < 1024; i += 256) Ws4[i] = Wg[i];
    if (tid < 64) {
        float s = g_stats[layer * 256 + tid];
        float q = g_stats[layer * 256 + 64 + tid];
        float mu = s * (1.f / NN);
        float var = q * (1.f / NN) - mu * mu;
        float a = rsqrtf(var + 1e-5f) * gam[tid];
        sA[tid] = a;
        sB[tid] = bet[tid] - mu * a;
        bs[tid] = b[tid];
    }
    __syncthreads();
    int n = blockIdx.x * 256 + tid;
    if (n >= NN) return;
    ull acc[32];
#pragma unroll
    for (int j = 0; j < 32; j++) acc[j] = pack2(bs[2 * j], bs[2 * j + 1]);
    const float4* z4 = ((const float4*)g_z1) + n * 16;
    const ulonglong2* Wv = (const ulonglong2*)Ws4;
#pragma unroll
    for (int kk = 0; kk < 16; kk++) {
        float4 v = z4[kk];
        int k0 = kk * 4;
        float y[4];
        y[0] = fmaxf(fmaf(v.x, sA[k0 + 0], sB[k0 + 0]), 0.f);
        y[1] = fmaxf(fmaf(v.y, sA[k0 + 1], sB[k0 + 1]), 0.f);
        y[2] = fmaxf(fmaf(v.z, sA[k0 + 2], sB[k0 + 2]), 0.f);
        y[3] = fmaxf(fmaf(v.w, sA[k0 + 3], sB[k0 + 3]), 0.f);
#pragma unroll
        for (int t2 = 0; t2 < 4; t2++) {
            ull a2 = pack2(y[t2], y[t2]);
            const ulonglong2* row = Wv + (k0 + t2) * 16;
#pragma unroll
            for (int jj = 0; jj < 16; jj++) {
                ulonglong2 w = row[jj];
                ffma2(acc[2 * jj], a2, w.x);
                ffma2(acc[2 * jj + 1], a2, w.y);
            }
        }
    }
    float4* o4 = ((float4*)g_z2) + n * 16;
#pragma unroll
    for (int m = 0; m < 16; m++) {
        float2 lo = unpack2(acc[2 * m]);
        float2 hi = unpack2(acc[2 * m + 1]);
        o4[m] = make_float4(lo.x, lo.y, hi.x, hi.y);
    }
}

// ---------------- BN2+relu -> h; logits += h @ fcW[layer+1] -------------------
__global__ void __launch_bounds__(256) kbn2(const float* __restrict__ gam,
                                            const float* __restrict__ bet,
                                            const float* __restrict__ fcW,
                                            int layer,
                                            float* __restrict__ out) {
    __shared__ float fw[640];
    __shared__ float sA[64], sB[64];
    int tid = threadIdx.x;
    const float* fsrc = fcW + (layer + 1) * 640;
    for (int i = tid; i < 640; i += 256) fw[i] = fsrc[i];
    if (tid < 64) {
        float s = g_stats[layer * 256 + 128 + tid];
        float q = g_stats[layer * 256 + 192 + tid];
        float mu = s * (1.f / NN);
        float var = q * (1.f / NN) - mu * mu;
        float a = rsqrtf(var + 1e-5f) * gam[tid];
        sA[tid] = a;
        sB[tid] = bet[tid] - mu * a;
    }
    __syncthreads();
    int n = blockIdx.x * 256 + tid;
    if (n >= NN) return;
    float o[10];
#pragma unroll
    for (int c = 0; c < 10; c++) o[c] = out[n * 10 + c];
    const float4* z4 = ((const float4*)g_z2) + n * 16;
    float4* hout = ((float4*)g_h) + n * 16;
#pragma unroll
    for (int kk = 0; kk < 16; kk++) {
        float4 v = z4[kk];
        int k0 = kk * 4;
        float h0 = fmaxf(fmaf(v.x, sA[k0 + 0], sB[k0 + 0]), 0.f);
        float h1 = fmaxf(fmaf(v.y, sA[k0 + 1], sB[k0 + 1]), 0.f);
        float h2 = fmaxf(fmaf(v.z, sA[k0 + 2], sB[k0 + 2]), 0.f);
        float h3 = fmaxf(fmaf(v.w, sA[k0 + 3], sB[k0 + 3]), 0.f);
        hout[kk] = make_float4(h0, h1, h2, h3);
        const float* r0 = fw + k0 * 10;
#pragma unroll
        for (int c = 0; c < 10; c++)
            o[c] += h0 * r0[c] + h1 * r0[10 + c] + h2 * r0[20 + c] + h3 * r0[30 + c];
    }
#pragma unroll
    for (int c = 0; c < 10; c++) out[n * 10 + c] = o[c];
}

// ---------------- final in-place log_softmax ----------------------------------
__global__ void __launch_bounds__(256) ksoftmax(float* __restrict__ out) {
    int n = blockIdx.x * 256 + threadIdx.x;
    if (n >= NN) return;
    float v[10];
    float m = -1e30f;
#pragma unroll
    for (int c = 0; c < 10; c++) {
        v[c] = out[n * 10 + c];
        m = fmaxf(m, v[c]);
    }
    float s = 0.f;
#pragma unroll
    for (int c = 0; c < 10; c++) s += expf(v[c] - m);
    float lse = m + logf(s);
#pragma unroll
    for (int c = 0; c < 10; c++) out[n * 10 + c] = v[c] - lse;
}

// ---------------- launch --------------------------------------------------------
extern "C" void kernel_launch(void* const* d_in, const int* in_sizes, int n_in,
                              void* d_out, int out_size) {
    const float* x   = (const float*)d_in[0];
    const int*   ei  = (const int*)d_in[1];   // edge_index (JAX default: int32)
    const float* W1  = (const float*)d_in[2];
    const float* b1  = (const float*)d_in[3];
    const float* g1  = (const float*)d_in[4];
    const float* be1 = (const float*)d_in[5];
    const float* W2  = (const float*)d_in[6];
    const float* b2  = (const float*)d_in[7];
    const float* gbn = (const float*)d_in[8];
    const float* bbn = (const float*)d_in[9];
    const float* fcW = (const float*)d_in[10];
    const float* fcb = (const float*)d_in[11];
    float* out = (float*)d_out;

    const int NB = (NN + 255) / 256;
    const int SB = (EE * 16) / 256;  // 100000 blocks

    kinit<<<NB, 256>>>(x, fcW, fcb, out);
    for (int l = 0; l < LL; l++) {
        int use_x = (l == 0) ? 1 : 0;
        kscatter<<<SB, 256>>>(ei, x, use_x);
        kgemm1<<<NB, 256>>>(x, use_x, W1 + l * 4096, b1 + l * 64);
        kstats<<<512, 256>>>(0, l);
        kgemm2<<<NB, 256>>>(W2 + l * 4096, b2 + l * 64, g1 + l * 64, be1 + l * 64, l);
        kstats<<<512, 256>>>(1, l);
        kbn2<<<NB, 256>>>(gbn + l * 64, bbn + l * 64, fcW, l, out);
    }
    ksoftmax<<<NB, 256>>>(out);
}

// round 2
// speedup vs baseline: 1.1725x; 1.1725x over previous
#include <cuda_runtime.h>

#define NN 100000
#define EE 1600000
#define LL 3
#define CAP 96

typedef unsigned long long ull;

// ---------------- device scratch (static) -------------------------------------
__device__ float g_h[NN * 64];        // current hidden state
__device__ float g_agg[NN * 64];      // gathered neighbor sums
__device__ float g_z1[NN * 64];       // pre-BN1 activations
__device__ float g_z2[NN * 64];       // pre-BN2 activations
__device__ float g_stats[LL * 256];   // per layer: [sum1(64) sq1(64) sum2(64) sq2(64)]
__device__ int   g_deg[NN];           // in-degree per node
__device__ int   g_csr[(size_t)NN * CAP];  // src lists grouped by dst, capacity CAP

// ---------------- packed f32x2 helpers ----------------------------------------
__device__ __forceinline__ ull pack2(float a, float b) {
    ull r;
    asm("mov.b64 %0, {%1, %2};" : "=l"(r) : "f"(a), "f"(b));
    return r;
}
__device__ __forceinline__ float2 unpack2(ull v) {
    float2 r;
    asm("mov.b64 {%0, %1}, %2;" : "=f"(r.x), "=f"(r.y) : "l"(v));
    return r;
}
__device__ __forceinline__ void ffma2(ull& d, ull a, ull b) {
    asm("fma.rn.f32x2 %0, %1, %2, %0;" : "+l"(d) : "l"(a), "l"(b));
}

// ---------------- zero degree + stats -----------------------------------------
__global__ void __launch_bounds__(1024) kzero() {
    int t = blockIdx.x * 1024 + threadIdx.x;
    if (t < NN) g_deg[t] = 0;
    if (t < LL * 256) g_stats[t] = 0.f;
}

// ---------------- CSR fill: bucket srcs by dst --------------------------------
__global__ void __launch_bounds__(256) kfill(const int* __restrict__ ei) {
    int e = blockIdx.x * 256 + threadIdx.x;
    if (e >= EE) return;
    int s = ei[e];
    int d = ei[EE + e];
    int pos = atomicAdd(&g_deg[d], 1);
    if (pos < CAP) g_csr[(size_t)d * CAP + pos] = s;
}

// ---------------- gather: agg[n] = sum over in-neighbors of h[src] ------------
__global__ void __launch_bounds__(256) kgather(const float* __restrict__ x, int use_x) {
    int w = (blockIdx.x * 256 + threadIdx.x) >> 5;
    int l = threadIdx.x & 31;
    if (w >= NN) return;
    const float* hin = use_x ? x : g_h;
    int deg = g_deg[w];
    if (deg > CAP) deg = CAP;
    const int* adj = g_csr + (size_t)w * CAP;
    float a0x = 0.f, a0y = 0.f, a1x = 0.f, a1y = 0.f;
    float a2x = 0.f, a2y = 0.f, a3x = 0.f, a3y = 0.f;
    int e = 0;
    for (; e + 4 <= deg; e += 4) {
        int i0 = adj[e], i1 = adj[e + 1], i2 = adj[e + 2], i3 = adj[e + 3];
        float2 v0 = *(const float2*)(hin + (size_t)i0 * 64 + 2 * l);
        float2 v1 = *(const float2*)(hin + (size_t)i1 * 64 + 2 * l);
        float2 v2 = *(const float2*)(hin + (size_t)i2 * 64 + 2 * l);
        float2 v3 = *(const float2*)(hin + (size_t)i3 * 64 + 2 * l);
        a0x += v0.x; a0y += v0.y;
        a1x += v1.x; a1y += v1.y;
        a2x += v2.x; a2y += v2.y;
        a3x += v3.x; a3y += v3.y;
    }
    for (; e < deg; e++) {
        int i0 = adj[e];
        float2 v0 = *(const float2*)(hin + (size_t)i0 * 64 + 2 * l);
        a0x += v0.x; a0y += v0.y;
    }
    float2 r;
    r.x = (a0x + a1x) + (a2x + a3x);
    r.y = (a0y + a1y) + (a2y + a3y);
    ((float2*)g_agg)[(size_t)w * 32 + l] = r;
}

// ---------------- K_init: logits = x @ fcW[0] + sum_l fcb[l] -------------------
__global__ void __launch_bounds__(256) kinit(const float* __restrict__ x,
                                             const float* __restrict__ fcW,
                                             const float* __restrict__ fcb,
                                             float* __restrict__ out) {
    __shared__ float fw[640];
    __shared__ float bsum[10];
    int tid = threadIdx.x;
    for (int i = tid; i < 640; i += 256) fw[i] = fcW[i];
    if (tid < 10) {
        float b = 0.f;
        for (int l = 0; l < LL + 1; l++) b += fcb[l * 10 + tid];
        bsum[tid] = b;
    }
    __syncthreads();
    int n = blockIdx.x * 256 + tid;
    if (n >= NN) return;
    float acc[10];
#pragma unroll
    for (int c = 0; c < 10; c++) acc[c] = bsum[c];
    const float4* x4 = ((const float4*)x) + n * 16;
#pragma unroll
    for (int kk = 0; kk < 16; kk++) {
        float4 v = x4[kk];
        const float* r0 = fw + (kk * 4) * 10;
#pragma unroll
        for (int c = 0; c < 10; c++)
            acc[c] += v.x * r0[c] + v.y * r0[10 + c] + v.z * r0[20 + c] + v.w * r0[30 + c];
    }
#pragma unroll
    for (int c = 0; c < 10; c++) out[n * 10 + c] = acc[c];
}

// ---------------- GEMM1: z1 = (h + agg) @ W1 + b1 ------------------------------
__global__ void __launch_bounds__(256) kgemm1(const float* __restrict__ x, int use_x,
                                              const float* __restrict__ W,
                                              const float* __restrict__ b) {
    __shared__ float4 Ws4[1024];
    __shared__ float bs[64];
    int tid = threadIdx.x;
    const float4* Wg = (const float4*)W;
    for (int i = tid; i < 1024; i += 256) Ws4[i] = Wg[i];
    if (tid < 64) bs[tid] = b[tid];
    __syncthreads();
    int n = blockIdx.x * 256 + tid;
    if (n >= NN) return;
    const float* hin = use_x ? x : g_h;
    ull acc[32];
#pragma unroll
    for (int j = 0; j < 32; j++) acc[j] = pack2(bs[2 * j], bs[2 * j + 1]);
    const float4* h4 = ((const float4*)hin) + n * 16;
    const float4* a4 = ((const float4*)g_agg) + n * 16;
    const ulonglong2* Wv = (const ulonglong2*)Ws4;
#pragma unroll
    for (int kk = 0; kk < 16; kk++) {
        float4 hv = h4[kk];
        float4 av = a4[kk];
        float y[4] = {hv.x + av.x, hv.y + av.y, hv.z + av.z, hv.w + av.w};
#pragma unroll
        for (int t2 = 0; t2 < 4; t2++) {
            ull a2 = pack2(y[t2], y[t2]);
            const ulonglong2* row = Wv + (kk * 4 + t2) * 16;
#pragma unroll
            for (int jj = 0; jj < 16; jj++) {
                ulonglong2 w = row[jj];
                ffma2(acc[2 * jj], a2, w.x);
                ffma2(acc[2 * jj + 1], a2, w.y);
            }
        }
    }
    float4* o4 = ((float4*)g_z1) + n * 16;
#pragma unroll
    for (int m = 0; m < 16; m++) {
        float2 lo = unpack2(acc[2 * m]);
        float2 hi = unpack2(acc[2 * m + 1]);
        o4[m] = make_float4(lo.x, lo.y, hi.x, hi.y);
    }
}

// ---------------- column sums + sums-of-squares (MLP-4 unrolled) ---------------
__global__ void __launch_bounds__(256) kstats(int which, int layer) {
    const float4* z4 = (const float4*)(which ? g_z2 : g_z1);
    float* sums = g_stats + layer * 256 + (which ? 128 : 0);
    __shared__ float4 shS[256];
    __shared__ float4 shQ[256];
    int tid = threadIdx.x;
    int c4 = tid & 15;
    int g = tid >> 4;
    const int ST = gridDim.x * 16;
    float4 s = make_float4(0.f, 0.f, 0.f, 0.f);
    float4 q = s;
    int r = blockIdx.x * 16 + g;
    for (; r + 3 * ST < NN; r += 4 * ST) {
        float4 v0 = z4[(size_t)r * 16 + c4];
        float4 v1 = z4[(size_t)(r + ST) * 16 + c4];
        float4 v2 = z4[(size_t)(r + 2 * ST) * 16 + c4];
        float4 v3 = z4[(size_t)(r + 3 * ST) * 16 + c4];
        s.x += v0.x + v1.x + v2.x + v3.x;
        s.y += v0.y + v1.y + v2.y + v3.y;
        s.z += v0.z + v1.z + v2.z + v3.z;
        s.w += v0.w + v1.w + v2.w + v3.w;
        q.x += v0.x * v0.x + v1.x * v1.x + v2.x * v2.x + v3.x * v3.x;
        q.y += v0.y * v0.y + v1.y * v1.y + v2.y * v2.y + v3.y * v3.y;
        q.z += v0.z * v0.z + v1.z * v1.z + v2.z * v2.z + v3.z * v3.z;
        q.w += v0.w * v0.w + v1.w * v1.w + v2.w * v2.w + v3.w * v3.w;
    }
    for (; r < NN; r += ST) {
        float4 v = z4[(size_t)r * 16 + c4];
        s.x += v.x; s.y += v.y; s.z += v.z; s.w += v.w;
        q.x += v.x * v.x; q.y += v.y * v.y; q.z += v.z * v.z; q.w += v.w * v.w;
    }
    shS[tid] = s;
    shQ[tid] = q;
    __syncthreads();
    if (g == 0) {
        for (int gg = 1; gg < 16; gg++) {
            float4 a = shS[c4 + 16 * gg];
            s.x += a.x; s.y += a.y; s.z += a.z; s.w += a.w;
            float4 bq = shQ[c4 + 16 * gg];
            q.x += bq.x; q.y += bq.y; q.z += bq.z; q.w += bq.w;
        }
        atomicAdd(&sums[c4 * 4 + 0], s.x);
        atomicAdd(&sums[c4 * 4 + 1], s.y);
        atomicAdd(&sums[c4 * 4 + 2], s.z);
        atomicAdd(&sums[c4 * 4 + 3], s.w);
        atomicAdd(&sums[64 + c4 * 4 + 0], q.x);
        atomicAdd(&sums[64 + c4 * 4 + 1], q.y);
        atomicAdd(&sums[64 + c4 * 4 + 2], q.z);
        atomicAdd(&sums[64 + c4 * 4 + 3], q.w);
    }
}

// ---------------- GEMM2: z2 = relu(BN1(z1)) @ W2 + b2 --------------------------
__global__ void __launch_bounds__(256) kgemm2(const float* __restrict__ W,
                                              const float* __restrict__ b,
                                              const float* __restrict__ gam,
                                              const float* __restrict__ bet,
                                              int layer) {
    __shared__ float4 Ws4[1024];
    __shared__ float bs[64], sA[64], sB[64];
    int tid = threadIdx.x;
    const float4* Wg = (const float4*)W;
    for (int i = tid; i < 1024; i += 256) Ws4[i] = Wg[i];
    if (tid < 64) {
        float s = g_stats[layer * 256 + tid];
        float q = g_stats[layer * 256 + 64 + tid];
        float mu = s * (1.f / NN);
        float var = q * (1.f / NN) - mu * mu;
        float a = rsqrtf(var + 1e-5f) * gam[tid];
        sA[tid] = a;
        sB[tid] = bet[tid] - mu * a;
        bs[tid] = b[tid];
    }
    __syncthreads();
    int n = blockIdx.x * 256 + tid;
    if (n >= NN) return;
    ull acc[32];
#pragma unroll
    for (int j = 0; j < 32; j++) acc[j] = pack2(bs[2 * j], bs[2 * j + 1]);
    const float4* z4 = ((const float4*)g_z1) + n * 16;
    const ulonglong2* Wv = (const ulonglong2*)Ws4;
#pragma unroll
    for (int kk = 0; kk < 16; kk++) {
        float4 v = z4[kk];
        int k0 = kk * 4;
        float y[4];
        y[0] = fmaxf(fmaf(v.x, sA[k0 + 0], sB[k0 + 0]), 0.f);
        y[1] = fmaxf(fmaf(v.y, sA[k0 + 1], sB[k0 + 1]), 0.f);
        y[2] = fmaxf(fmaf(v.z, sA[k0 + 2], sB[k0 + 2]), 0.f);
        y[3] = fmaxf(fmaf(v.w, sA[k0 + 3], sB[k0 + 3]), 0.f);
#pragma unroll
        for (int t2 = 0; t2 < 4; t2++) {
            ull a2 = pack2(y[t2], y[t2]);
            const ulonglong2* row = Wv + (k0 + t2) * 16;
#pragma unroll
            for (int jj = 0; jj < 16; jj++) {
                ulonglong2 w = row[jj];
                ffma2(acc[2 * jj], a2, w.x);
                ffma2(acc[2 * jj + 1], a2, w.y);
            }
        }
    }
    float4* o4 = ((float4*)g_z2) + n * 16;
#pragma unroll
    for (int m = 0; m < 16; m++) {
        float2 lo = unpack2(acc[2 * m]);
        float2 hi = unpack2(acc[2 * m + 1]);
        o4[m] = make_float4(lo.x, lo.y, hi.x, hi.y);
    }
}

// -------- BN2+relu -> h; logits += h @ fcW[layer+1]; optional log-softmax ------
__global__ void __launch_bounds__(256) kbn2(const float* __restrict__ gam,
                                            const float* __restrict__ bet,
                                            const float* __restrict__ fcW,
                                            int layer, int final_layer,
                                            float* __restrict__ out) {
    __shared__ float fw[640];
    __shared__ float sA[64], sB[64];
    int tid = threadIdx.x;
    const float* fsrc = fcW + (layer + 1) * 640;
    for (int i = tid; i < 640; i += 256) fw[i] = fsrc[i];
    if (tid < 64) {
        float s = g_stats[layer * 256 + 128 + tid];
        float q = g_stats[layer * 256 + 192 + tid];
        float mu = s * (1.f / NN);
        float var = q * (1.f / NN) - mu * mu;
        float a = rsqrtf(var + 1e-5f) * gam[tid];
        sA[tid] = a;
        sB[tid] = bet[tid] - mu * a;
    }
    __syncthreads();
    int n = blockIdx.x * 256 + tid;
    if (n >= NN) return;
    float o[10];
#pragma unroll
    for (int c = 0; c < 10; c++) o[c] = out[n * 10 + c];
    const float4* z4 = ((const float4*)g_z2) + n * 16;
    float4* hout = ((float4*)g_h) + n * 16;
#pragma unroll
    for (int kk = 0; kk < 16; kk++) {
        float4 v = z4[kk];
        int k0 = kk * 4;
        float h0 = fmaxf(fmaf(v.x, sA[k0 + 0], sB[k0 + 0]), 0.f);
        float h1 = fmaxf(fmaf(v.y, sA[k0 + 1], sB[k0 + 1]), 0.f);
        float h2 = fmaxf(fmaf(v.z, sA[k0 + 2], sB[k0 + 2]), 0.f);
        float h3 = fmaxf(fmaf(v.w, sA[k0 + 3], sB[k0 + 3]), 0.f);
        if (!final_layer) hout[kk] = make_float4(h0, h1, h2, h3);
        const float* r0 = fw + k0 * 10;
#pragma unroll
        for (int c = 0; c < 10; c++)
            o[c] += h0 * r0[c] + h1 * r0[10 + c] + h2 * r0[20 + c] + h3 * r0[30 + c];
    }
    if (final_layer) {
        float m = -1e30f;
#pragma unroll
        for (int c = 0; c < 10; c++) m = fmaxf(m, o[c]);
        float s = 0.f;
#pragma unroll
        for (int c = 0; c < 10; c++) s += expf(o[c] - m);
        float lse = m + logf(s);
#pragma unroll
        for (int c = 0; c < 10; c++) o[c] -= lse;
    }
#pragma unroll
    for (int c = 0; c < 10; c++) out[n * 10 + c] = o[c];
}

// ---------------- launch --------------------------------------------------------
extern "C" void kernel_launch(void* const* d_in, const int* in_sizes, int n_in,
                              void* d_out, int out_size) {
    const float* x   = (const float*)d_in[0];
    const int*   ei  = (const int*)d_in[1];
    const float* W1  = (const float*)d_in[2];
    const float* b1  = (const float*)d_in[3];
    const float* g1  = (const float*)d_in[4];
    const float* be1 = (const float*)d_in[5];
    const float* W2  = (const float*)d_in[6];
    const float* b2  = (const float*)d_in[7];
    const float* gbn = (const float*)d_in[8];
    const float* bbn = (const float*)d_in[9];
    const float* fcW = (const float*)d_in[10];
    const float* fcb = (const float*)d_in[11];
    float* out = (float*)d_out;

    const int NB = (NN + 255) / 256;          // 391
    const int GB = (NN * 32 + 255) / 256;     // warp-per-node gather: 12500

    kzero<<<(NN + 1023) / 1024, 1024>>>();
    kfill<<<(EE + 255) / 256, 256>>>(ei);
    kinit<<<NB, 256>>>(x, fcW, fcb, out);
    for (int l = 0; l < LL; l++) {
        int use_x = (l == 0) ? 1 : 0;
        kgather<<<GB, 256>>>(x, use_x);
        kgemm1<<<NB, 256>>>(x, use_x, W1 + l * 4096, b1 + l * 64);
        kstats<<<740, 256>>>(0, l);
        kgemm2<<<NB, 256>>>(W2 + l * 4096, b2 + l * 64, g1 + l * 64, be1 + l * 64, l);
        kstats<<<740, 256>>>(1, l);
        kbn2<<<NB, 256>>>(gbn + l * 64, bbn + l * 64, fcW, l, (l == LL - 1) ? 1 : 0, out);
    }
}